// round 4
// baseline (speedup 1.0000x reference)
#include <cuda_runtime.h>
#include <stdint.h>

// Problem shape (from reference): D = 64 floats per row -> 16 float4 per row.
#define D4 16           // float4 per row
#define MAX_NODES 262144

__device__ float g_counts[MAX_NODES];
__device__ float g_inv[MAX_NODES];
__device__ int   g_is64;   // 1 if edge_index is int64, 0 if int32

__device__ __forceinline__ void red_add_v4(float* addr, float4 v) {
    asm volatile("red.global.add.v4.f32 [%0], {%1, %2, %3, %4};"
                 :: "l"(addr), "f"(v.x), "f"(v.y), "f"(v.z), "f"(v.w)
                 : "memory");
}

// Detect edge_index dtype. For int64 data with values in [0, n_nodes), every
// odd 32-bit word is a (zero) high word. For int32 data, odd words are random
// node ids; the chance 64 of them are all zero is ~0.
__global__ void na_detect_kernel(const int* __restrict__ ei_words) {
    int acc = ei_words[1 + 2 * threadIdx.x];   // odd words 1,3,...,127
    #pragma unroll
    for (int off = 16; off > 0; off >>= 1)
        acc |= __shfl_xor_sync(0xffffffffu, acc, off);
    if (threadIdx.x == 0) g_is64 = (acc == 0) ? 1 : 0;
}

// counts = 1 (self-loop)
__global__ void na_count_init_kernel(int n_nodes) {
    int i = blockIdx.x * blockDim.x + threadIdx.x;
    if (i < n_nodes) g_counts[i] = 1.0f;
}

// one thread per edge: in-degree accumulation
__global__ void na_count_kernel(const void* __restrict__ ei_raw, int n_edges) {
    int e = blockIdx.x * blockDim.x + threadIdx.x;
    if (e >= n_edges) return;
    int dst;
    if (g_is64) dst = (int)__ldg((const long long*)ei_raw + n_edges + e);
    else        dst = __ldg((const int*)ei_raw + n_edges + e);
    atomicAdd(&g_counts[dst], 1.0f);
}

// reciprocal of in-degree (always >= 1 due to self-loop)
__global__ void na_recip_kernel(int n_nodes) {
    int i = blockIdx.x * blockDim.x + threadIdx.x;
    if (i < n_nodes) g_inv[i] = 1.0f / g_counts[i];
}

// Init: pre-scaled self-loop contribution (out = Z * inv).
__global__ void na_init_kernel(const float4* __restrict__ Zr,
                               const float4* __restrict__ Zi,
                               float4* __restrict__ outr,
                               float4* __restrict__ outi,
                               int total4) {
    int i = blockIdx.x * blockDim.x + threadIdx.x;
    if (i >= total4) return;
    float inv = g_inv[i >> 4];   // row = i / 16
    float4 r = Zr[i];
    float4 m = Zi[i];
    r.x *= inv; r.y *= inv; r.z *= inv; r.w *= inv;
    m.x *= inv; m.y *= inv; m.z *= inv; m.w *= inv;
    outr[i] = r;
    outi[i] = m;
}

// One warp per edge. Lanes 0-15: real row float4s, lanes 16-31: imag row.
// Contribution pre-scaled by 1/indeg(dst) so no normalize pass is needed.
__global__ void na_edge_kernel(const float4* __restrict__ Zr,
                               const float4* __restrict__ Zi,
                               const void* __restrict__ ei_raw,
                               float4* __restrict__ outr,
                               float4* __restrict__ outi,
                               int n_edges) {
    int warp = (blockIdx.x * blockDim.x + threadIdx.x) >> 5;
    if (warp >= n_edges) return;
    int lane = threadIdx.x & 31;

    // warp-uniform index loads (all lanes same address -> L1 broadcast)
    int src, dst;
    if (g_is64) {
        const long long* ei = (const long long*)ei_raw;
        src = (int)__ldg(ei + warp);
        dst = (int)__ldg(ei + n_edges + warp);
    } else {
        const int* ei = (const int*)ei_raw;
        src = __ldg(ei + warp);
        dst = __ldg(ei + n_edges + warp);
    }

    float inv = __ldg(&g_inv[dst]);   // warp-uniform, cached

    int c = lane & 15;
    const float4* srcp;
    float4* dstp;
    if (lane < 16) { srcp = Zr; dstp = outr; }
    else           { srcp = Zi; dstp = outi; }

    float4 v = __ldg(srcp + (size_t)src * D4 + c);
    v.x *= inv; v.y *= inv; v.z *= inv; v.w *= inv;
    red_add_v4((float*)(dstp + (size_t)dst * D4 + c), v);
}

extern "C" void kernel_launch(void* const* d_in, const int* in_sizes, int n_in,
                              void* d_out, int out_size) {
    const float4* Zr = (const float4*)d_in[0];
    const float4* Zi = (const float4*)d_in[1];
    const void*   ei = d_in[2];

    int n_nodes = in_sizes[0] / 64;          // D = 64
    int n_edges = in_sizes[2] / 2;           // edge_index is (2, E), elem count
    int total4  = n_nodes * D4;              // float4 elements per output array

    float* out = (float*)d_out;
    float4* outr = (float4*)out;                               // first half: A_real
    float4* outi = (float4*)(out + (size_t)n_nodes * 64);      // second half: A_imag

    const int T = 256;

    // 0) dtype detection (1 warp)
    na_detect_kernel<<<1, 64>>>((const int*)ei);

    // 1) in-degree: counts=1 then += per edge, then reciprocal
    na_count_init_kernel<<<(n_nodes + T - 1) / T, T>>>(n_nodes);
    na_count_kernel<<<(n_edges + T - 1) / T, T>>>(ei, n_edges);
    na_recip_kernel<<<(n_nodes + T - 1) / T, T>>>(n_nodes);

    // 2) init: out = Z * inv (self-loop, pre-scaled)
    na_init_kernel<<<(total4 + T - 1) / T, T>>>(Zr, Zi, outr, outi, total4);

    // 3) edge scatter-add of pre-scaled contributions
    long long threads_needed = (long long)n_edges * 32;
    int blocks = (int)((threads_needed + T - 1) / T);
    na_edge_kernel<<<blocks, T>>>(Zr, Zi, ei, outr, outi, n_edges);
}

// round 5
// speedup vs baseline: 2.1376x; 2.1376x over previous
#include <cuda_runtime.h>
#include <stdint.h>

#define D4 16                  // float4 per 64-float row
#define MAX_NODES 262144
#define MAX_EDGES 2097152
#define SCAN_T 256             // scanA block size
#define FULL 0xffffffffu

__device__ int   g_deg[MAX_NODES];
__device__ int   g_cur[MAX_NODES];
__device__ int   g_off[MAX_NODES];
__device__ int   g_bsum[MAX_NODES / SCAN_T + 2];
__device__ float g_inv[MAX_NODES];
__device__ int   g_src_sorted[MAX_EDGES];
__device__ int   g_is64;

// ---------- dtype detection (int64 hi-words are all zero for ids < 100000) ----------
__global__ void na_detect_kernel(const int* __restrict__ ei_words) {
    int acc = ei_words[1 + 2 * threadIdx.x];   // odd words 1..127
    #pragma unroll
    for (int off = 16; off > 0; off >>= 1)
        acc |= __shfl_xor_sync(FULL, acc, off);
    if (threadIdx.x == 0) g_is64 = (acc == 0) ? 1 : 0;
}

__device__ __forceinline__ int load_idx(const void* ei, int n_edges, int which, int e) {
    if (g_is64) return (int)__ldg((const long long*)ei + (size_t)which * n_edges + e);
    return __ldg((const int*)ei + (size_t)which * n_edges + e);
}

// ---------- build CSR ----------
__global__ void na_zero_kernel(int n_nodes) {
    int i = blockIdx.x * blockDim.x + threadIdx.x;
    if (i < n_nodes) { g_deg[i] = 0; g_cur[i] = 0; }
}

__global__ void na_count_kernel(const void* __restrict__ ei, int n_edges) {
    int e = blockIdx.x * blockDim.x + threadIdx.x;
    if (e >= n_edges) return;
    atomicAdd(&g_deg[load_idx(ei, n_edges, 1, e)], 1);
}

// per-block exclusive scan of g_deg -> g_off (partial), block totals -> g_bsum
__global__ void na_scanA_kernel(int n_nodes) {
    __shared__ int s[SCAN_T];
    int i = blockIdx.x * SCAN_T + threadIdx.x;
    int v = (i < n_nodes) ? g_deg[i] : 0;
    s[threadIdx.x] = v;
    __syncthreads();
    // Hillis-Steele inclusive scan
    #pragma unroll
    for (int off = 1; off < SCAN_T; off <<= 1) {
        int add = (threadIdx.x >= off) ? s[threadIdx.x - off] : 0;
        __syncthreads();
        s[threadIdx.x] += add;
        __syncthreads();
    }
    if (i < n_nodes) g_off[i] = s[threadIdx.x] - v;   // exclusive
    if (threadIdx.x == SCAN_T - 1) g_bsum[blockIdx.x] = s[SCAN_T - 1];
}

// single-block exclusive scan of block sums (up to 1024 blocks)
__global__ void na_scanB_kernel(int nblocks) {
    __shared__ int s[1024];
    int t = threadIdx.x;
    int v = (t < nblocks) ? g_bsum[t] : 0;
    s[t] = v;
    __syncthreads();
    #pragma unroll
    for (int off = 1; off < 1024; off <<= 1) {
        int add = (t >= off) ? s[t - off] : 0;
        __syncthreads();
        s[t] += add;
        __syncthreads();
    }
    if (t < nblocks) g_bsum[t] = s[t] - v;   // exclusive
}

// fixup offsets + reciprocal of (deg+1)
__global__ void na_scanC_kernel(int n_nodes) {
    int i = blockIdx.x * blockDim.x + threadIdx.x;
    if (i >= n_nodes) return;
    g_off[i] += g_bsum[i / SCAN_T];
    g_inv[i] = 1.0f / (float)(g_deg[i] + 1);
}

// bucket src ids by dst
__global__ void na_scatter_kernel(const void* __restrict__ ei, int n_edges) {
    int e = blockIdx.x * blockDim.x + threadIdx.x;
    if (e >= n_edges) return;
    int src = load_idx(ei, n_edges, 0, e);
    int dst = load_idx(ei, n_edges, 1, e);
    int pos = g_off[dst] + atomicAdd(&g_cur[dst], 1);
    g_src_sorted[pos] = src;
}

// ---------- pull-mode gather: one warp per node, register accumulation ----------
__global__ void na_gather_kernel(const float4* __restrict__ Zr,
                                 const float4* __restrict__ Zi,
                                 float4* __restrict__ outr,
                                 float4* __restrict__ outi,
                                 int n_nodes) {
    int node = (blockIdx.x * blockDim.x + threadIdx.x) >> 5;
    if (node >= n_nodes) return;
    int lane = threadIdx.x & 31;
    int c = lane & 15;

    const float4* srcp = (lane < 16) ? Zr : Zi;
    float4* dstp       = (lane < 16) ? outr : outi;

    int off = g_off[node];
    int deg = g_deg[node];

    // self-loop seed
    float4 acc = __ldg(srcp + (size_t)node * D4 + c);

    for (int j0 = 0; j0 < deg; j0 += 32) {
        int rem = deg - j0;
        int m = (rem < 32) ? rem : 32;
        int myid = (lane < m) ? __ldg(&g_src_sorted[off + j0 + lane]) : 0;
        for (int j = 0; j < m; j++) {
            int src = __shfl_sync(FULL, myid, j);
            float4 v = __ldg(srcp + (size_t)src * D4 + c);
            acc.x += v.x; acc.y += v.y; acc.z += v.z; acc.w += v.w;
        }
    }

    float inv = g_inv[node];
    acc.x *= inv; acc.y *= inv; acc.z *= inv; acc.w *= inv;
    dstp[(size_t)node * D4 + c] = acc;
}

extern "C" void kernel_launch(void* const* d_in, const int* in_sizes, int n_in,
                              void* d_out, int out_size) {
    const float4* Zr = (const float4*)d_in[0];
    const float4* Zi = (const float4*)d_in[1];
    const void*   ei = d_in[2];

    int n_nodes = in_sizes[0] / 64;
    int n_edges = in_sizes[2] / 2;

    float* out = (float*)d_out;
    float4* outr = (float4*)out;
    float4* outi = (float4*)(out + (size_t)n_nodes * 64);

    const int T = 256;
    int nb_nodes = (n_nodes + T - 1) / T;
    int nb_edges = (n_edges + T - 1) / T;
    int nb_scan  = (n_nodes + SCAN_T - 1) / SCAN_T;

    na_detect_kernel<<<1, 64>>>((const int*)ei);
    na_zero_kernel<<<nb_nodes, T>>>(n_nodes);
    na_count_kernel<<<nb_edges, T>>>(ei, n_edges);
    na_scanA_kernel<<<nb_scan, SCAN_T>>>(n_nodes);
    na_scanB_kernel<<<1, 1024>>>(nb_scan);
    na_scanC_kernel<<<nb_nodes, T>>>(n_nodes);
    na_scatter_kernel<<<nb_edges, T>>>(ei, n_edges);

    long long gather_threads = (long long)n_nodes * 32;
    int nb_gather = (int)((gather_threads + T - 1) / T);
    na_gather_kernel<<<nb_gather, T>>>(Zr, Zi, outr, outi, n_nodes);
}